// round 15
// baseline (speedup 1.0000x reference)
#include <cuda_runtime.h>
#include <cstdint>

#define NROWS   8192
#define KDIM    512
#define NPCAS   128
#define NSTACKS 64
#define OUTDIM  8192

#define COEFF_F   3.7712361663282537f
#define TWO_PI_F  6.283185307179586f

__device__ float g_xproj[NROWS * NPCAS];

// ---------------------------------------------------------------------------
// Kernel 1: unchanged from R14 (bit-exact; 32 rows/block).
// ---------------------------------------------------------------------------
__global__ __launch_bounds__(256, 2)
void gemm_kernel(const float* __restrict__ A, const float* __restrict__ B,
                 float* __restrict__ C)
{
    __shared__ float As[32 * 64];
    __shared__ float Bs[64 * 128];

    const int tid  = threadIdx.x;
    const int r0   = blockIdx.x * 32;
    const int warp = tid >> 5;
    const int lane = tid & 31;
    const int rbase = warp * 4;
    const int cb    = lane * 4;

    float acc[4][4];
#pragma unroll
    for (int i = 0; i < 4; i++)
#pragma unroll
        for (int j = 0; j < 4; j++) acc[i][j] = 0.0f;

    for (int kc = 0; kc < KDIM; kc += 64) {
        __syncthreads();
#pragma unroll
        for (int i = 0; i < 2; i++) {
            int idx = tid + i * 256;
            int row = idx >> 4;
            int k4  = idx & 15;
            ((float4*)As)[row * 16 + k4] =
                *(const float4*)(A + (size_t)(r0 + row) * KDIM + kc + k4 * 4);
        }
#pragma unroll
        for (int i = 0; i < 8; i++) {
            int idx = tid + i * 256;
            int kk  = idx >> 5;
            int c4  = idx & 31;
            ((float4*)Bs)[kk * 32 + c4] =
                *(const float4*)(B + (size_t)(kc + kk) * NPCAS + c4 * 4);
        }
        __syncthreads();

#pragma unroll 8
        for (int kk = 0; kk < 64; kk++) {
            float4 b4 = ((const float4*)Bs)[kk * 32 + lane];
#pragma unroll
            for (int i = 0; i < 4; i++) {
                float a = As[(rbase + i) * 64 + kk];
                acc[i][0] = fmaf(a, b4.x, acc[i][0]);
                acc[i][1] = fmaf(a, b4.y, acc[i][1]);
                acc[i][2] = fmaf(a, b4.z, acc[i][2]);
                acc[i][3] = fmaf(a, b4.w, acc[i][3]);
            }
        }
    }

#pragma unroll
    for (int i = 0; i < 4; i++) {
        float4 v = make_float4(acc[i][0], acc[i][1], acc[i][2], acc[i][3]);
        *(float4*)(C + (size_t)(r0 + rbase + i) * NPCAS + cb) = v;
    }
}

// ---------------------------------------------------------------------------
// Packed f32x2 helpers. R7 lesson: never emit packed mul.rn feeding packed
// add.rn where two roundings are required — ptxas fuses them into fma.
// ---------------------------------------------------------------------------
typedef unsigned long long u64t;

__device__ __forceinline__ u64t pack2(float lo, float hi) {
    u64t r; asm("mov.b64 %0, {%1, %2};" : "=l"(r) : "f"(lo), "f"(hi)); return r;
}
__device__ __forceinline__ void unpack2(u64t v, float& lo, float& hi) {
    asm("mov.b64 {%0, %1}, %2;" : "=f"(lo), "=f"(hi) : "l"(v));
}
__device__ __forceinline__ u64t fma2(u64t a, u64t b, u64t c) {
    u64t r; asm("fma.rn.f32x2 %0, %1, %2, %3;" : "=l"(r) : "l"(a), "l"(b), "l"(c)); return r;
}
__device__ __forceinline__ u64t mul2(u64t a, u64t b) {
    u64t r; asm("mul.rn.f32x2 %0, %1, %2;" : "=l"(r) : "l"(a), "l"(b)); return r;
}

// Packed cos, per-half bit-identical to the scalar fast_cos (R4-verified).
__device__ __forceinline__ void fast_cos2(u64t X, float& o0, float& o1)
{
    const u64t INV2   = pack2(0.6366197723675814f, 0.6366197723675814f);
    const u64t MAG2   = pack2(12582912.0f, 12582912.0f);
    const u64t NMAG2  = pack2(-12582912.0f, -12582912.0f);
    const u64t NPIH2  = pack2(-1.5707963705062866f, -1.5707963705062866f);
    const u64t PIL2   = pack2(4.3711388286737929e-8f, 4.3711388286737929e-8f);
    const u64t CC3    = pack2(2.443315711809948e-5f, 2.443315711809948e-5f);
    const u64t CC2    = pack2(-1.388731625493765e-3f, -1.388731625493765e-3f);
    const u64t CC1    = pack2(4.166664568298827e-2f, 4.166664568298827e-2f);
    const u64t CHALF  = pack2(-0.5f, -0.5f);
    const u64t CONE   = pack2(1.0f, 1.0f);
    const u64t SS3    = pack2(-1.9515295891e-4f, -1.9515295891e-4f);
    const u64t SS2    = pack2(8.3321608736e-3f, 8.3321608736e-3f);
    const u64t SS1    = pack2(-1.6666654611e-1f, -1.6666654611e-1f);

    u64t T = fma2(X, INV2, MAG2);
    float tlo, thi; unpack2(T, tlo, thi);
    int q0 = __float_as_int(tlo);
    int q1 = __float_as_int(thi);
    u64t Q = fma2(T, CONE, NMAG2);   // exact (Sterbenz), single rounding
    u64t R = fma2(Q, NPIH2, X);
    R = fma2(Q, PIL2, R);
    u64t S = mul2(R, R);             // feeds fma2 only — fusion-safe

    u64t PC = fma2(S, CC3, CC2);
    PC = fma2(S, PC, CC1);
    PC = fma2(S, PC, CHALF);
    PC = fma2(S, PC, CONE);

    u64t PS = fma2(S, SS3, SS2);
    PS = fma2(S, PS, SS1);
    u64t SR = mul2(S, R);            // feeds fma2 as multiplicand — safe
    PS = fma2(PS, SR, R);

    float pc0, pc1, ps0, ps1;
    unpack2(PC, pc0, pc1);
    unpack2(PS, ps0, ps1);

    float v0 = (q0 & 1) ? ps0 : pc0;
    float v1 = (q1 & 1) ? ps1 : pc1;
    o0 = __int_as_float(__float_as_int(v0) ^ (int)(((unsigned)(q0 + 1) & 2u) << 30));
    o1 = __int_as_float(__float_as_int(v1) ^ (int)(((unsigned)(q1 + 1) & 2u) << 30));
}

__device__ __forceinline__ float xor_signw(float f, unsigned w)
{
    return __int_as_float(__float_as_int(f) ^ ((int)w & 0x80000000));
}

// 128-pt FWHT across warp, 4 elems/lane (best-measured layout).
__device__ __forceinline__ void fwht_core(float& f0, float& f1, float& f2, float& f3,
                                          unsigned d0, unsigned d1, unsigned d2, unsigned d3,
                                          const float sg1, const float sg2, const float sg4,
                                          const float sg8, const float sg16)
{
    f0 = xor_signw(f0, d0); f1 = xor_signw(f1, d1);
    f2 = xor_signw(f2, d2); f3 = xor_signw(f3, d3);
    float t0 = f0 + f1, t1 = f0 - f1, t2 = f2 + f3, t3 = f2 - f3;
    f0 = t0 + t2; f1 = t1 + t3; f2 = t0 - t2; f3 = t1 - t3;
    {
        float p0 = __shfl_xor_sync(0xffffffffu, f0, 1);
        float p1 = __shfl_xor_sync(0xffffffffu, f1, 1);
        float p2 = __shfl_xor_sync(0xffffffffu, f2, 1);
        float p3 = __shfl_xor_sync(0xffffffffu, f3, 1);
        f0 = fmaf(sg1, f0, p0); f1 = fmaf(sg1, f1, p1);
        f2 = fmaf(sg1, f2, p2); f3 = fmaf(sg1, f3, p3);
    }
    {
        float p0 = __shfl_xor_sync(0xffffffffu, f0, 2);
        float p1 = __shfl_xor_sync(0xffffffffu, f1, 2);
        float p2 = __shfl_xor_sync(0xffffffffu, f2, 2);
        float p3 = __shfl_xor_sync(0xffffffffu, f3, 2);
        f0 = fmaf(sg2, f0, p0); f1 = fmaf(sg2, f1, p1);
        f2 = fmaf(sg2, f2, p2); f3 = fmaf(sg2, f3, p3);
    }
    {
        float p0 = __shfl_xor_sync(0xffffffffu, f0, 4);
        float p1 = __shfl_xor_sync(0xffffffffu, f1, 4);
        float p2 = __shfl_xor_sync(0xffffffffu, f2, 4);
        float p3 = __shfl_xor_sync(0xffffffffu, f3, 4);
        f0 = fmaf(sg4, f0, p0); f1 = fmaf(sg4, f1, p1);
        f2 = fmaf(sg4, f2, p2); f3 = fmaf(sg4, f3, p3);
    }
    {
        float p0 = __shfl_xor_sync(0xffffffffu, f0, 8);
        float p1 = __shfl_xor_sync(0xffffffffu, f1, 8);
        float p2 = __shfl_xor_sync(0xffffffffu, f2, 8);
        float p3 = __shfl_xor_sync(0xffffffffu, f3, 8);
        f0 = fmaf(sg8, f0, p0); f1 = fmaf(sg8, f1, p1);
        f2 = fmaf(sg8, f2, p2); f3 = fmaf(sg8, f3, p3);
    }
    {
        float p0 = __shfl_xor_sync(0xffffffffu, f0, 16);
        float p1 = __shfl_xor_sync(0xffffffffu, f1, 16);
        float p2 = __shfl_xor_sync(0xffffffffu, f2, 16);
        float p3 = __shfl_xor_sync(0xffffffffu, f3, 16);
        f0 = fmaf(sg16, f0, p0); f1 = fmaf(sg16, f1, p1);
        f2 = fmaf(sg16, f2, p2); f3 = fmaf(sg16, f3, p3);
    }
}

// ---------------------------------------------------------------------------
// Kernel 2: item = (row, stack-pair). K2_NW ≡ 0 (mod 32) makes the stack-pair
// loop-invariant per warp, so d-sign words and b·2π are hoisted out of the
// grid-stride loop (kills ~12 of ~56 MIO wavefronts per stack-visit).
// ---------------------------------------------------------------------------
#define K2_BLOCKS  592          // 148 * 4
#define K2_THREADS 256
#define K2_NW      (K2_BLOCKS * K2_THREADS / 32)   // 4736 = 32*148
#define NITEMS     (NROWS * 32)

__global__ __launch_bounds__(K2_THREADS)
void fwht_cos_kernel(const float* __restrict__ xp, const float* __restrict__ d,
                     const float* __restrict__ b, float* __restrict__ out)
{
    const int lane = threadIdx.x & 31;
    const int gw   = (blockIdx.x * K2_THREADS + threadIdx.x) >> 5;
    const int e    = lane * 4;

    const float sg1  = (lane & 1)  ? -1.0f : 1.0f;
    const float sg2  = (lane & 2)  ? -1.0f : 1.0f;
    const float sg4  = (lane & 4)  ? -1.0f : 1.0f;
    const float sg8  = (lane & 8)  ? -1.0f : 1.0f;
    const float sg16 = (lane & 16) ? -1.0f : 1.0f;

    // stack pair for this warp — invariant across the grid-stride loop
    const int sp = gw & 31;          // item & 31 == gw & 31 (K2_NW % 32 == 0)
    const int s0 = sp * 2;

    // hoisted d-sign words and b*2pi for both stacks of the pair
    unsigned w0[2][4], w1[2][4];
    float    bb[2][4];
#pragma unroll
    for (int p = 0; p < 2; p++) {
        const int base = (s0 + p) * NPCAS + e;
        uint4 q0 = *(const uint4*)(d + base);
        uint4 q1 = *(const uint4*)(d + NSTACKS * NPCAS + base);
        float4 bv = *(const float4*)(b + base);
        w0[p][0] = q0.x; w0[p][1] = q0.y; w0[p][2] = q0.z; w0[p][3] = q0.w;
        w1[p][0] = q1.x; w1[p][1] = q1.y; w1[p][2] = q1.z; w1[p][3] = q1.w;
        bb[p][0] = __fmul_rn(bv.x, TWO_PI_F);
        bb[p][1] = __fmul_rn(bv.y, TWO_PI_F);
        bb[p][2] = __fmul_rn(bv.z, TWO_PI_F);
        bb[p][3] = __fmul_rn(bv.w, TWO_PI_F);
    }

    for (int item = gw; item < NITEMS; item += K2_NW) {
        const int r = item >> 5;

        float4 xv = *(const float4*)(xp + (size_t)r * NPCAS + e);
        float* orow = out + (size_t)r * OUTDIM;

#pragma unroll
        for (int p = 0; p < 2; p++) {
            const int s = s0 + p;

            float f0 = xv.x, f1 = xv.y, f2 = xv.z, f3 = xv.w;

            fwht_core(f0, f1, f2, f3, w0[p][0], w0[p][1], w0[p][2], w0[p][3],
                      sg1, sg2, sg4, sg8, sg16);
            f0 = __fmul_rn(f0, COEFF_F); f1 = __fmul_rn(f1, COEFF_F);
            f2 = __fmul_rn(f2, COEFF_F); f3 = __fmul_rn(f3, COEFF_F);

            fwht_core(f0, f1, f2, f3, w1[p][0], w1[p][1], w1[p][2], w1[p][3],
                      sg1, sg2, sg4, sg8, sg16);

            // SEPARATE scalar mul then add (two roundings) — matches reference
            float a0 = __fadd_rn(__fmul_rn(f0, COEFF_F), bb[p][0]);
            float a1 = __fadd_rn(__fmul_rn(f1, COEFF_F), bb[p][1]);
            float a2 = __fadd_rn(__fmul_rn(f2, COEFF_F), bb[p][2]);
            float a3 = __fadd_rn(__fmul_rn(f3, COEFF_F), bb[p][3]);

            float4 ov;
            fast_cos2(pack2(a0, a1), ov.x, ov.y);
            fast_cos2(pack2(a2, a3), ov.z, ov.w);

            *(float4*)(orow + s * NPCAS + e) = ov;
        }
    }
}

// ---------------------------------------------------------------------------
extern "C" void kernel_launch(void* const* d_in, const int* in_sizes, int n_in,
                              void* d_out, int out_size)
{
    const float* x    = (const float*)d_in[0];
    const float* proj = (const float*)d_in[1];
    const float* d    = (const float*)d_in[2];
    const float* b    = (const float*)d_in[3];
    float* out        = (float*)d_out;

    float* xproj;
    cudaGetSymbolAddress((void**)&xproj, g_xproj);

    gemm_kernel<<<NROWS / 32, 256>>>(x, proj, xproj);
    fwht_cos_kernel<<<K2_BLOCKS, K2_THREADS>>>(xproj, d, b, out);
}